// round 13
// baseline (speedup 1.0000x reference)
#include <cuda_runtime.h>

// R12 architecture (single-wave plain-LDG + shuffle for shifted pred) with
// the wave size corrected to the true register limit: regs=36 -> 7 CTAs/SM,
// so one wave = 148*7 = 1036 CTAs. __launch_bounds__(256,7) pins regalloc
// at <=36 regs so the grid stays exactly one wave.
// Fused "last block finishes" finalize, deterministic.

static constexpr int BLOCKS  = 148 * 7;   // 1036 CTAs = exactly 1 wave @ 36 regs
static constexpr int THREADS = 256;

__device__ float        g_partials[BLOCKS];
__device__ unsigned int g_done_count;      // zero-init; reset each call

__global__ __launch_bounds__(THREADS, 7) void trajloss_wave7_kernel(
    const float* __restrict__ pred,   // N+1 elements
    const float* __restrict__ xs,     // N elements
    const float* __restrict__ ys,     // N elements
    float* __restrict__ out,
    int n4)                           // N / 4
{
    const float4* __restrict__ pred4 = reinterpret_cast<const float4*>(pred);
    const float4* __restrict__ x4    = reinterpret_cast<const float4*>(xs);
    const float4* __restrict__ y4    = reinterpret_cast<const float4*>(ys);

    float acc0 = 0.0f, acc1 = 0.0f;

    const int stride = BLOCKS * THREADS;
    const int lane   = threadIdx.x & 31;
    int idx = blockIdx.x * THREADS + threadIdx.x;

    // stride % 32 == 0 and warp bases are 32-aligned -> multiple-of-32 bound
    // keeps the loop guard warp-uniform (shuffle-safe).
    const int bound = n4 & ~31;

    #pragma unroll 4
    for (int i = idx; i < bound; i += stride) {
        float4 p  = pred4[i];
        float4 xv = __ldcs(&x4[i]);
        float4 yv = __ldcs(&y4[i]);

        // pred[4i+4] = next lane's p.x; lane 31 loads across the warp boundary.
        float pn = __shfl_down_sync(0xFFFFFFFFu, p.x, 1);
        if (lane == 31) pn = __ldg(&pred[i * 4 + 4]);

        float dx0 = xv.x - p.x, dx1 = xv.y - p.y;
        float dx2 = xv.z - p.z, dx3 = xv.w - p.w;
        float dy0 = yv.x - p.y, dy1 = yv.y - p.z;
        float dy2 = yv.z - p.w, dy3 = yv.w - pn;

        acc0 = fmaf(dx0, dx0, acc0); acc1 = fmaf(dy0, dy0, acc1);
        acc0 = fmaf(dx1, dx1, acc0); acc1 = fmaf(dy1, dy1, acc1);
        acc0 = fmaf(dx2, dx2, acc0); acc1 = fmaf(dy2, dy2, acc1);
        acc0 = fmaf(dx3, dx3, acc0); acc1 = fmaf(dy3, dy3, acc1);
    }

    // Shuffle-free remainder (zero iterations for N = 2^24).
    for (int i = (idx >= bound ? idx : idx + ((bound - idx + stride - 1) / stride) * stride);
         i < n4; i += stride) {
        float4 p  = pred4[i];
        float4 xv = __ldcs(&x4[i]);
        float4 yv = __ldcs(&y4[i]);
        float  pn = __ldg(&pred[i * 4 + 4]);

        float dx0 = xv.x - p.x, dx1 = xv.y - p.y;
        float dx2 = xv.z - p.z, dx3 = xv.w - p.w;
        float dy0 = yv.x - p.y, dy1 = yv.y - p.z;
        float dy2 = yv.z - p.w, dy3 = yv.w - pn;

        acc0 = fmaf(dx0, dx0, acc0); acc1 = fmaf(dy0, dy0, acc1);
        acc0 = fmaf(dx1, dx1, acc0); acc1 = fmaf(dy1, dy1, acc1);
        acc0 = fmaf(dx2, dx2, acc0); acc1 = fmaf(dy2, dy2, acc1);
        acc0 = fmaf(dx3, dx3, acc0); acc1 = fmaf(dy3, dy3, acc1);
    }

    float acc = acc0 + acc1;

    // ---- intra-block reduction ----
    #pragma unroll
    for (int off = 16; off > 0; off >>= 1)
        acc += __shfl_xor_sync(0xFFFFFFFFu, acc, off);

    __shared__ float warp_sums[THREADS / 32];
    __shared__ bool  is_last;
    int wid = threadIdx.x >> 5;
    if (lane == 0) warp_sums[wid] = acc;
    __syncthreads();

    if (wid == 0) {
        float v = (lane < THREADS / 32) ? warp_sums[lane] : 0.0f;
        #pragma unroll
        for (int off = 4; off > 0; off >>= 1)
            v += __shfl_xor_sync(0xFFFFFFFFu, v, off);
        if (lane == 0) {
            g_partials[blockIdx.x] = v;
            __threadfence();
            unsigned int prev = atomicAdd(&g_done_count, 1u);
            is_last = (prev == (unsigned int)(BLOCKS - 1));
        }
    }
    __syncthreads();

    // ---- last block reduces all partials ----
    if (is_last) {
        float t = 0.0f;
        for (int k = threadIdx.x; k < BLOCKS; k += THREADS)
            t += g_partials[k];

        #pragma unroll
        for (int off = 16; off > 0; off >>= 1)
            t += __shfl_xor_sync(0xFFFFFFFFu, t, off);

        if (lane == 0) warp_sums[wid] = t;
        __syncthreads();

        if (wid == 0) {
            float v = (lane < THREADS / 32) ? warp_sums[lane] : 0.0f;
            #pragma unroll
            for (int off = 4; off > 0; off >>= 1)
                v += __shfl_xor_sync(0xFFFFFFFFu, v, off);
            if (lane == 0) {
                out[0] = v;
                g_done_count = 0;     // graph-replay safe reset
            }
        }
    }
}

extern "C" void kernel_launch(void* const* d_in, const int* in_sizes, int n_in,
                              void* d_out, int out_size)
{
    const float* pred = (const float*)d_in[0];   // N+1
    const float* xs   = (const float*)d_in[1];   // N
    const float* ys   = (const float*)d_in[2];   // N
    float* out        = (float*)d_out;

    int n  = in_sizes[1];
    int n4 = n >> 2;

    trajloss_wave7_kernel<<<BLOCKS, THREADS>>>(pred, xs, ys, out, n4);
}

// round 14
// speedup vs baseline: 1.0466x; 1.0466x over previous
#include <cuda_runtime.h>

// R12 (wallclock-best: single-wave 888-CTA plain-LDG + shuffle for the
// shifted pred element, unroll 4) with __launch_bounds__(256, 6):
//  - locks 6 CTAs/SM so 888 CTAs is exactly one wave BY CONSTRUCTION
//    (R12 relied on ptxas happening to pick 36 regs);
//  - grants ptxas up to 42 regs (vs 36) of scheduling freedom for deeper
//    load batching in the unrolled body.
// R13 showed regs/warp >> warp count for this loop; this moves regs up, not down.
// Fused "last block finishes" finalize, deterministic.

static constexpr int BLOCKS  = 148 * 6;   // 888 CTAs = exactly 1 wave @ 6 CTAs/SM
static constexpr int THREADS = 256;

__device__ float        g_partials[BLOCKS];
__device__ unsigned int g_done_count;      // zero-init; reset each call

__global__ __launch_bounds__(THREADS, 6) void trajloss_wave6_kernel(
    const float* __restrict__ pred,   // N+1 elements
    const float* __restrict__ xs,     // N elements
    const float* __restrict__ ys,     // N elements
    float* __restrict__ out,
    int n4)                           // N / 4
{
    const float4* __restrict__ pred4 = reinterpret_cast<const float4*>(pred);
    const float4* __restrict__ x4    = reinterpret_cast<const float4*>(xs);
    const float4* __restrict__ y4    = reinterpret_cast<const float4*>(ys);

    float acc0 = 0.0f, acc1 = 0.0f;

    const int stride = BLOCKS * THREADS;
    const int lane   = threadIdx.x & 31;
    int idx = blockIdx.x * THREADS + threadIdx.x;

    // stride % 32 == 0 and warp bases are 32-aligned -> multiple-of-32 bound
    // keeps the loop guard warp-uniform (shuffle-safe).
    const int bound = n4 & ~31;

    #pragma unroll 4
    for (int i = idx; i < bound; i += stride) {
        float4 p  = pred4[i];
        float4 xv = __ldcs(&x4[i]);
        float4 yv = __ldcs(&y4[i]);

        // pred[4i+4] = next lane's p.x; lane 31 loads across the warp boundary.
        float pn = __shfl_down_sync(0xFFFFFFFFu, p.x, 1);
        if (lane == 31) pn = __ldg(&pred[i * 4 + 4]);

        float dx0 = xv.x - p.x, dx1 = xv.y - p.y;
        float dx2 = xv.z - p.z, dx3 = xv.w - p.w;
        float dy0 = yv.x - p.y, dy1 = yv.y - p.z;
        float dy2 = yv.z - p.w, dy3 = yv.w - pn;

        acc0 = fmaf(dx0, dx0, acc0); acc1 = fmaf(dy0, dy0, acc1);
        acc0 = fmaf(dx1, dx1, acc0); acc1 = fmaf(dy1, dy1, acc1);
        acc0 = fmaf(dx2, dx2, acc0); acc1 = fmaf(dy2, dy2, acc1);
        acc0 = fmaf(dx3, dx3, acc0); acc1 = fmaf(dy3, dy3, acc1);
    }

    // Shuffle-free remainder (zero iterations for N = 2^24).
    for (int i = (idx >= bound ? idx : idx + ((bound - idx + stride - 1) / stride) * stride);
         i < n4; i += stride) {
        float4 p  = pred4[i];
        float4 xv = __ldcs(&x4[i]);
        float4 yv = __ldcs(&y4[i]);
        float  pn = __ldg(&pred[i * 4 + 4]);

        float dx0 = xv.x - p.x, dx1 = xv.y - p.y;
        float dx2 = xv.z - p.z, dx3 = xv.w - p.w;
        float dy0 = yv.x - p.y, dy1 = yv.y - p.z;
        float dy2 = yv.z - p.w, dy3 = yv.w - pn;

        acc0 = fmaf(dx0, dx0, acc0); acc1 = fmaf(dy0, dy0, acc1);
        acc0 = fmaf(dx1, dx1, acc0); acc1 = fmaf(dy1, dy1, acc1);
        acc0 = fmaf(dx2, dx2, acc0); acc1 = fmaf(dy2, dy2, acc1);
        acc0 = fmaf(dx3, dx3, acc0); acc1 = fmaf(dy3, dy3, acc1);
    }

    float acc = acc0 + acc1;

    // ---- intra-block reduction ----
    #pragma unroll
    for (int off = 16; off > 0; off >>= 1)
        acc += __shfl_xor_sync(0xFFFFFFFFu, acc, off);

    __shared__ float warp_sums[THREADS / 32];
    __shared__ bool  is_last;
    int wid = threadIdx.x >> 5;
    if (lane == 0) warp_sums[wid] = acc;
    __syncthreads();

    if (wid == 0) {
        float v = (lane < THREADS / 32) ? warp_sums[lane] : 0.0f;
        #pragma unroll
        for (int off = 4; off > 0; off >>= 1)
            v += __shfl_xor_sync(0xFFFFFFFFu, v, off);
        if (lane == 0) {
            g_partials[blockIdx.x] = v;
            __threadfence();
            unsigned int prev = atomicAdd(&g_done_count, 1u);
            is_last = (prev == (unsigned int)(BLOCKS - 1));
        }
    }
    __syncthreads();

    // ---- last block reduces all partials ----
    if (is_last) {
        float t = 0.0f;
        for (int k = threadIdx.x; k < BLOCKS; k += THREADS)
            t += g_partials[k];

        #pragma unroll
        for (int off = 16; off > 0; off >>= 1)
            t += __shfl_xor_sync(0xFFFFFFFFu, t, off);

        if (lane == 0) warp_sums[wid] = t;
        __syncthreads();

        if (wid == 0) {
            float v = (lane < THREADS / 32) ? warp_sums[lane] : 0.0f;
            #pragma unroll
            for (int off = 4; off > 0; off >>= 1)
                v += __shfl_xor_sync(0xFFFFFFFFu, v, off);
            if (lane == 0) {
                out[0] = v;
                g_done_count = 0;     // graph-replay safe reset
            }
        }
    }
}

extern "C" void kernel_launch(void* const* d_in, const int* in_sizes, int n_in,
                              void* d_out, int out_size)
{
    const float* pred = (const float*)d_in[0];   // N+1
    const float* xs   = (const float*)d_in[1];   // N
    const float* ys   = (const float*)d_in[2];   // N
    float* out        = (float*)d_out;

    int n  = in_sizes[1];
    int n4 = n >> 2;

    trajloss_wave6_kernel<<<BLOCKS, THREADS>>>(pred, xs, ys, out, n4);
}